// round 4
// baseline (speedup 1.0000x reference)
#include <cuda_runtime.h>
#include <cstdint>

// ============================================================================
// Problem constants
// ============================================================================
#define N_NODES 10000
#define N_EDGES 160000
#define D_IN    512
#define D_HID   1024

// ============================================================================
// Scratch (static __device__ arrays — no allocation allowed)
// ============================================================================
__device__ float g_rst[(size_t)N_NODES * D_IN];     // GIN combine output  [N, 512]
__device__ float g_H  [(size_t)N_NODES * D_HID];    // hidden after relu   [N, 1024]
__device__ float g_Wt1[(size_t)D_HID * D_IN];       // W1^T  [1024, 512]
__device__ float g_Wt2[(size_t)D_IN * D_HID];       // W2^T  [512, 1024]
__device__ int   g_cnt[N_NODES];
__device__ int   g_off[N_NODES + 1];
__device__ int   g_cur[N_NODES];
__device__ int   g_csr[N_EDGES];

// ============================================================================
// Helpers
// ============================================================================
__device__ __forceinline__ uint32_t smem_to_u32(const void* p) {
    uint32_t a;
    asm("{ .reg .u64 t; cvta.to.shared.u64 t, %1; cvt.u32.u64 %0, t; }" : "=r"(a) : "l"(p));
    return a;
}

// ============================================================================
// Graph preprocessing kernels (CSR build)
// ============================================================================
__global__ void zero_cnt_kernel() {
    int i = blockIdx.x * blockDim.x + threadIdx.x;
    if (i < N_NODES) g_cnt[i] = 0;
}

__global__ void hist_kernel(const int* __restrict__ dst) {
    int i = blockIdx.x * blockDim.x + threadIdx.x;
    if (i < N_EDGES) atomicAdd(&g_cnt[dst[i]], 1);
}

__global__ void scan_kernel() {
    __shared__ int s[1024];
    __shared__ int s_tot;
    int tid = threadIdx.x;
    int base = 0;
    for (int c0 = 0; c0 < N_NODES; c0 += 1024) {
        int i = c0 + tid;
        int v = (i < N_NODES) ? g_cnt[i] : 0;
        s[tid] = v;
        __syncthreads();
        for (int o = 1; o < 1024; o <<= 1) {
            int t = (tid >= o) ? s[tid - o] : 0;
            __syncthreads();
            s[tid] += t;
            __syncthreads();
        }
        if (i < N_NODES) { int ex = base + s[tid] - v; g_off[i] = ex; g_cur[i] = ex; }
        if (tid == 1023) s_tot = s[1023];
        __syncthreads();
        base += s_tot;
        __syncthreads();
    }
    if (tid == 0) g_off[N_NODES] = base;
}

__global__ void scatter_kernel(const int* __restrict__ src, const int* __restrict__ dst) {
    int i = blockIdx.x * blockDim.x + threadIdx.x;
    if (i < N_EDGES) {
        int d = dst[i];
        int p = atomicAdd(&g_cur[d], 1);
        g_csr[p] = src[i];
    }
}

// ============================================================================
// Aggregate: warp-per-node gather-sum + GIN combine -> g_rst
// ============================================================================
__device__ __forceinline__ void f4add(float4& a, const float4 b) {
    a.x += b.x; a.y += b.y; a.z += b.z; a.w += b.w;
}

__global__ __launch_bounds__(256) void aggregate_kernel(const float* __restrict__ feat,
                                                        const float* __restrict__ eps) {
    int wid = threadIdx.x >> 5, lane = threadIdx.x & 31;
    int node = blockIdx.x * 8 + wid;
    if (node >= N_NODES) return;

    float4 a0 = make_float4(0.f, 0.f, 0.f, 0.f), a1 = a0, a2 = a0, a3 = a0;
    int e = g_off[node], e1 = g_off[node + 1];
    const float4* F = (const float4*)feat;

    for (; e + 1 < e1; e += 2) {
        const float4* p0 = F + (size_t)g_csr[e]     * (D_IN / 4);
        const float4* p1 = F + (size_t)g_csr[e + 1] * (D_IN / 4);
        float4 v00 = p0[lane], v01 = p0[lane + 32], v02 = p0[lane + 64], v03 = p0[lane + 96];
        float4 v10 = p1[lane], v11 = p1[lane + 32], v12 = p1[lane + 64], v13 = p1[lane + 96];
        f4add(a0, v00); f4add(a1, v01); f4add(a2, v02); f4add(a3, v03);
        f4add(a0, v10); f4add(a1, v11); f4add(a2, v12); f4add(a3, v13);
    }
    if (e < e1) {
        const float4* p0 = F + (size_t)g_csr[e] * (D_IN / 4);
        f4add(a0, p0[lane]); f4add(a1, p0[lane + 32]);
        f4add(a2, p0[lane + 64]); f4add(a3, p0[lane + 96]);
    }

    float ep = 1.0f + eps[0];
    const float4* fn = F + (size_t)node * (D_IN / 4);
    float4* R = (float4*)g_rst + (size_t)node * (D_IN / 4);
    float4 f0 = fn[lane], f1 = fn[lane + 32], f2 = fn[lane + 64], f3 = fn[lane + 96];
    R[lane]      = make_float4(fmaf(ep, f0.x, a0.x), fmaf(ep, f0.y, a0.y), fmaf(ep, f0.z, a0.z), fmaf(ep, f0.w, a0.w));
    R[lane + 32] = make_float4(fmaf(ep, f1.x, a1.x), fmaf(ep, f1.y, a1.y), fmaf(ep, f1.z, a1.z), fmaf(ep, f1.w, a1.w));
    R[lane + 64] = make_float4(fmaf(ep, f2.x, a2.x), fmaf(ep, f2.y, a2.y), fmaf(ep, f2.z, a2.z), fmaf(ep, f2.w, a2.w));
    R[lane + 96] = make_float4(fmaf(ep, f3.x, a3.x), fmaf(ep, f3.y, a3.y), fmaf(ep, f3.z, a3.z), fmaf(ep, f3.w, a3.w));
}

// ============================================================================
// Weight transpose: out[c][r] = in[r][c]   (in: [R, C] row-major)
// ============================================================================
__global__ void transpose_kernel(const float* __restrict__ in, float* __restrict__ out,
                                 int R, int C) {
    __shared__ float t[32][33];
    int bx = blockIdx.x * 32, by = blockIdx.y * 32;
    int tx = threadIdx.x, ty = threadIdx.y;
    #pragma unroll
    for (int j = 0; j < 32; j += 8)
        t[ty + j][tx] = in[(size_t)(by + ty + j) * C + bx + tx];
    __syncthreads();
    #pragma unroll
    for (int j = 0; j < 32; j += 8)
        out[(size_t)(bx + ty + j) * R + by + tx] = t[tx][ty + j];
}

// ============================================================================
// 3xTF32 mma.sync GEMM: out[M,N] = act(A[M,K] @ Bt[N,K]^T + bias) (+ residual)
// BM=128, BN=128, BK=32, 256 threads (8 warps as 2x4), cp.async double buffer.
// Error-compensated tf32: a = a_hi(tf32-exact) + a_lo;
//   acc += A_hi*B_hi + A_hi*B_lo + A_lo*B_hi   (lo*lo term ~2^-22, dropped)
// ============================================================================
#define BM 128
#define BN 128
#define BK 32
#define BKPAD 36                  // 32 + 4 pad -> conflict-free frag LDS
#define TILE_F (BM * BKPAD)       // floats per tile
#define TILE_B (TILE_F * 4)       // bytes per tile (18432)
#define GEMM_SMEM (4 * TILE_B)    // 2 stages x (A + B) = 73728

__device__ __forceinline__ void cp_async16(uint32_t dst, const void* src, int src_sz) {
    asm volatile("cp.async.ca.shared.global [%0], [%1], 16, %2;"
                 :: "r"(dst), "l"(src), "r"(src_sz));
}

__device__ __forceinline__ void load_tile(uint32_t sA, uint32_t sB,
                                          const float* __restrict__ A,
                                          const float* __restrict__ Bt,
                                          int M, int K, int m0, int n0, int k0, int tid) {
    #pragma unroll
    for (int i = 0; i < 4; i++) {
        int idx = tid + i * 256;
        int row = idx >> 3, c4 = idx & 7;
        int gm = m0 + row;
        int ok = gm < M;
        const float* gp = A + (size_t)(ok ? gm : 0) * K + k0 + c4 * 4;
        cp_async16(sA + (uint32_t)(row * BKPAD + c4 * 4) * 4, gp, ok ? 16 : 0);
    }
    #pragma unroll
    for (int i = 0; i < 4; i++) {
        int idx = tid + i * 256;
        int row = idx >> 3, c4 = idx & 7;
        const float* gp = Bt + (size_t)(n0 + row) * K + k0 + c4 * 4;
        cp_async16(sB + (uint32_t)(row * BKPAD + c4 * 4) * 4, gp, 16);
    }
}

__device__ __forceinline__ void mma_tf32(float d[4], const uint32_t a[4],
                                         const uint32_t b[2]) {
    asm volatile(
        "mma.sync.aligned.m16n8k8.row.col.f32.tf32.tf32.f32 "
        "{%0,%1,%2,%3}, {%4,%5,%6,%7}, {%8,%9}, {%0,%1,%2,%3};"
        : "+f"(d[0]), "+f"(d[1]), "+f"(d[2]), "+f"(d[3])
        : "r"(a[0]), "r"(a[1]), "r"(a[2]), "r"(a[3]), "r"(b[0]), "r"(b[1]));
}

// hi = exact tf32 (low 13 mantissa bits zeroed); lo = exact fp32 remainder.
__device__ __forceinline__ void split_tf32(uint32_t raw, uint32_t& hi, uint32_t& lo) {
    hi = raw & 0xFFFFE000u;
    lo = __float_as_uint(__uint_as_float(raw) - __uint_as_float(hi));
}

__global__ __launch_bounds__(256) void gemm_tf32_kernel(
    const float* __restrict__ A, const float* __restrict__ Bt,
    const float* __restrict__ bias, const float* __restrict__ residual,
    float* __restrict__ out, int M, int K, int N, int do_relu)
{
    extern __shared__ float smem[];
    uint32_t sb = smem_to_u32(smem);
    const int tid = threadIdx.x, wid = tid >> 5, lane = tid & 31;
    const int m0 = blockIdx.y * BM, n0 = blockIdx.x * BN;
    const int wm = wid & 1, wn = wid >> 1;       // warp tile: 64 (m) x 32 (n)
    const int lg = lane >> 2, lt = lane & 3;     // group / thread-in-group

    // smem layout: [A0][A1][B0][B1]
    const uint32_t sA[2] = {sb, sb + TILE_B};
    const uint32_t sB[2] = {sb + 2 * TILE_B, sb + 3 * TILE_B};
    const uint32_t* smA = (const uint32_t*)smem;
    const uint32_t* smB = (const uint32_t*)smem + 2 * TILE_F;

    float acc[4][4][4];
    #pragma unroll
    for (int i = 0; i < 4; i++)
        #pragma unroll
        for (int j = 0; j < 4; j++)
            #pragma unroll
            for (int c = 0; c < 4; c++) acc[i][j][c] = 0.f;

    const int nk = K / BK;
    load_tile(sA[0], sB[0], A, Bt, M, K, m0, n0, 0, tid);
    asm volatile("cp.async.commit_group;" ::: "memory");
    if (nk > 1) load_tile(sA[1], sB[1], A, Bt, M, K, m0, n0, BK, tid);
    asm volatile("cp.async.commit_group;" ::: "memory");

    for (int kc = 0; kc < nk; kc++) {
        asm volatile("cp.async.wait_group 1;" ::: "memory");
        __syncthreads();
        const int buf = kc & 1;
        const uint32_t* tA = smA + buf * TILE_F;
        const uint32_t* tB = smB + buf * TILE_F;

        #pragma unroll
        for (int kk = 0; kk < BK; kk += 8) {
            // ---- B fragments: load + split once per kk
            uint32_t bhi[4][2], blo[4][2];
            #pragma unroll
            for (int nj = 0; nj < 4; nj++) {
                int n = wn * 32 + nj * 8 + lg;
                const uint32_t* p = tB + n * BKPAD + kk + lt;
                split_tf32(p[0], bhi[nj][0], blo[nj][0]);
                split_tf32(p[4], bhi[nj][1], blo[nj][1]);
            }
            // ---- A fragments per mi; 3 MMAs per (mi,nj)
            #pragma unroll
            for (int mi = 0; mi < 4; mi++) {
                int r0 = wm * 64 + mi * 16 + lg;
                const uint32_t* p = tA + r0 * BKPAD + kk + lt;
                uint32_t ahi[4], alo[4];
                split_tf32(p[0],            ahi[0], alo[0]);
                split_tf32(p[8 * BKPAD],    ahi[1], alo[1]);
                split_tf32(p[4],            ahi[2], alo[2]);
                split_tf32(p[8 * BKPAD + 4], ahi[3], alo[3]);
                #pragma unroll
                for (int nj = 0; nj < 4; nj++) {
                    mma_tf32(acc[mi][nj], ahi, blo[nj]);   // hi*lo
                    mma_tf32(acc[mi][nj], alo, bhi[nj]);   // lo*hi
                    mma_tf32(acc[mi][nj], ahi, bhi[nj]);   // hi*hi
                }
            }
        }
        __syncthreads();
        if (kc + 2 < nk)
            load_tile(sA[buf], sB[buf], A, Bt, M, K, m0, n0, (kc + 2) * BK, tid);
        asm volatile("cp.async.commit_group;" ::: "memory");
    }

    // ---- Epilogue: bias + optional relu + optional residual, float2 stores
    #pragma unroll
    for (int mi = 0; mi < 4; mi++) {
        #pragma unroll
        for (int half = 0; half < 2; half++) {
            int gm = m0 + wm * 64 + mi * 16 + lg + half * 8;
            if (gm >= M) continue;
            #pragma unroll
            for (int nj = 0; nj < 4; nj++) {
                int gn = n0 + wn * 32 + nj * 8 + 2 * lt;
                float vx = acc[mi][nj][half * 2 + 0];
                float vy = acc[mi][nj][half * 2 + 1];
                float2 bv = *(const float2*)(bias + gn);
                vx += bv.x; vy += bv.y;
                if (do_relu) { vx = fmaxf(vx, 0.f); vy = fmaxf(vy, 0.f); }
                if (residual) {
                    float2 rv = *(const float2*)(residual + (size_t)gm * N + gn);
                    vx += rv.x; vy += rv.y;
                }
                *(float2*)(out + (size_t)gm * N + gn) = make_float2(vx, vy);
            }
        }
    }
}

// ============================================================================
// kernel_launch
// ============================================================================
extern "C" void kernel_launch(void* const* d_in, const int* in_sizes, int n_in,
                              void* d_out, int out_size) {
    const float* feat = (const float*)d_in[0];
    const float* W1   = (const float*)d_in[1];
    const float* b1   = (const float*)d_in[2];
    const float* W2   = (const float*)d_in[3];
    const float* b2   = (const float*)d_in[4];
    const float* eps  = (const float*)d_in[5];
    const int*   src  = (const int*)d_in[6];
    const int*   dst  = (const int*)d_in[7];
    float* out = (float*)d_out;

    float *p_rst, *p_H, *p_Wt1, *p_Wt2;
    cudaGetSymbolAddress((void**)&p_rst, g_rst);
    cudaGetSymbolAddress((void**)&p_H,   g_H);
    cudaGetSymbolAddress((void**)&p_Wt1, g_Wt1);
    cudaGetSymbolAddress((void**)&p_Wt2, g_Wt2);

    cudaFuncSetAttribute(gemm_tf32_kernel,
                         cudaFuncAttributeMaxDynamicSharedMemorySize, GEMM_SMEM);

    // --- CSR build
    zero_cnt_kernel<<<(N_NODES + 255) / 256, 256>>>();
    hist_kernel<<<N_EDGES / 256, 256>>>(dst);
    scan_kernel<<<1, 1024>>>();
    scatter_kernel<<<N_EDGES / 256, 256>>>(src, dst);

    // --- Weight transposes
    transpose_kernel<<<dim3(D_HID / 32, D_IN / 32), dim3(32, 8)>>>(W1, p_Wt1, D_IN, D_HID);
    transpose_kernel<<<dim3(D_IN / 32, D_HID / 32), dim3(32, 8)>>>(W2, p_Wt2, D_HID, D_IN);

    // --- Aggregate + GIN combine
    aggregate_kernel<<<(N_NODES + 7) / 8, 256>>>(feat, eps);

    // --- GEMM1: H = relu(rst @ W1 + b1)   [10000,512]@[512,1024]
    gemm_tf32_kernel<<<dim3(D_HID / BN, (N_NODES + BM - 1) / BM), 256, GEMM_SMEM>>>(
        p_rst, p_Wt1, b1, nullptr, p_H, N_NODES, D_IN, D_HID, 1);

    // --- GEMM2: out = H @ W2 + b2 + feat  [10000,1024]@[1024,512]
    gemm_tf32_kernel<<<dim3(D_IN / BN, (N_NODES + BM - 1) / BM), 256, GEMM_SMEM>>>(
        p_H, p_Wt2, b2, feat, out, N_NODES, D_HID, D_IN, 0);
}

// round 5
// speedup vs baseline: 1.3457x; 1.3457x over previous
#include <cuda_runtime.h>
#include <cuda_fp16.h>
#include <cstdint>

// ============================================================================
// Problem constants
// ============================================================================
#define N_NODES 10000
#define N_EDGES 160000
#define D_IN    512
#define D_HID   1024

// ============================================================================
// Scratch (static __device__ arrays — no allocation allowed)
// All operands pre-split into hi/lo fp16 pairs (3xFP16 compensated GEMM).
// ============================================================================
__device__ __half g_Ah[(size_t)N_NODES * D_IN];    // rst hi   [N, 512]
__device__ __half g_Al[(size_t)N_NODES * D_IN];    // rst lo
__device__ __half g_Hh[(size_t)N_NODES * D_HID];   // hidden hi [N, 1024]
__device__ __half g_Hl[(size_t)N_NODES * D_HID];   // hidden lo
__device__ __half g_W1h[(size_t)D_HID * D_IN];     // W1^T hi [1024, 512]
__device__ __half g_W1l[(size_t)D_HID * D_IN];
__device__ __half g_W2h[(size_t)D_IN * D_HID];     // W2^T hi [512, 1024]
__device__ __half g_W2l[(size_t)D_IN * D_HID];
__device__ int   g_cnt[N_NODES];
__device__ int   g_off[N_NODES + 1];
__device__ int   g_cur[N_NODES];
__device__ int   g_csr[N_EDGES];

// ============================================================================
// Helpers
// ============================================================================
__device__ __forceinline__ uint32_t smem_to_u32(const void* p) {
    uint32_t a;
    asm("{ .reg .u64 t; cvta.to.shared.u64 t, %1; cvt.u32.u64 %0, t; }" : "=r"(a) : "l"(p));
    return a;
}

__device__ __forceinline__ void split_h(float x, __half& h, __half& l) {
    h = __float2half_rn(x);
    l = __float2half_rn(x - __half2float(h));
}

// ============================================================================
// Graph preprocessing kernels (CSR build)
// ============================================================================
__global__ void zero_cnt_kernel() {
    int i = blockIdx.x * blockDim.x + threadIdx.x;
    if (i < N_NODES) g_cnt[i] = 0;
}

__global__ void hist_kernel(const int* __restrict__ dst) {
    int i = blockIdx.x * blockDim.x + threadIdx.x;
    if (i < N_EDGES) atomicAdd(&g_cnt[dst[i]], 1);
}

__global__ void scan_kernel() {
    __shared__ int s[1024];
    __shared__ int s_tot;
    int tid = threadIdx.x;
    int base = 0;
    for (int c0 = 0; c0 < N_NODES; c0 += 1024) {
        int i = c0 + tid;
        int v = (i < N_NODES) ? g_cnt[i] : 0;
        s[tid] = v;
        __syncthreads();
        for (int o = 1; o < 1024; o <<= 1) {
            int t = (tid >= o) ? s[tid - o] : 0;
            __syncthreads();
            s[tid] += t;
            __syncthreads();
        }
        if (i < N_NODES) { int ex = base + s[tid] - v; g_off[i] = ex; g_cur[i] = ex; }
        if (tid == 1023) s_tot = s[1023];
        __syncthreads();
        base += s_tot;
        __syncthreads();
    }
    if (tid == 0) g_off[N_NODES] = base;
}

__global__ void scatter_kernel(const int* __restrict__ src, const int* __restrict__ dst) {
    int i = blockIdx.x * blockDim.x + threadIdx.x;
    if (i < N_EDGES) {
        int d = dst[i];
        int p = atomicAdd(&g_cur[d], 1);
        g_csr[p] = src[i];
    }
}

// ============================================================================
// Aggregate: warp-per-node gather-sum + GIN combine -> split hi/lo fp16
// ============================================================================
__device__ __forceinline__ void f4add(float4& a, const float4 b) {
    a.x += b.x; a.y += b.y; a.z += b.z; a.w += b.w;
}

__device__ __forceinline__ void store_split4(__half* ph, __half* pl, size_t off, float4 v) {
    __half hx, hy, hz, hw, lx, ly, lz, lw;
    split_h(v.x, hx, lx); split_h(v.y, hy, ly);
    split_h(v.z, hz, lz); split_h(v.w, hw, lw);
    *(__half2*)(ph + off)     = __halves2half2(hx, hy);
    *(__half2*)(ph + off + 2) = __halves2half2(hz, hw);
    *(__half2*)(pl + off)     = __halves2half2(lx, ly);
    *(__half2*)(pl + off + 2) = __halves2half2(lz, lw);
}

__global__ __launch_bounds__(256) void aggregate_kernel(const float* __restrict__ feat,
                                                        const float* __restrict__ eps) {
    int wid = threadIdx.x >> 5, lane = threadIdx.x & 31;
    int node = blockIdx.x * 8 + wid;
    if (node >= N_NODES) return;

    float4 a0 = make_float4(0.f, 0.f, 0.f, 0.f), a1 = a0, a2 = a0, a3 = a0;
    int e = g_off[node], e1 = g_off[node + 1];
    const float4* F = (const float4*)feat;

    for (; e + 1 < e1; e += 2) {
        const float4* p0 = F + (size_t)g_csr[e]     * (D_IN / 4);
        const float4* p1 = F + (size_t)g_csr[e + 1] * (D_IN / 4);
        float4 v00 = p0[lane], v01 = p0[lane + 32], v02 = p0[lane + 64], v03 = p0[lane + 96];
        float4 v10 = p1[lane], v11 = p1[lane + 32], v12 = p1[lane + 64], v13 = p1[lane + 96];
        f4add(a0, v00); f4add(a1, v01); f4add(a2, v02); f4add(a3, v03);
        f4add(a0, v10); f4add(a1, v11); f4add(a2, v12); f4add(a3, v13);
    }
    if (e < e1) {
        const float4* p0 = F + (size_t)g_csr[e] * (D_IN / 4);
        f4add(a0, p0[lane]); f4add(a1, p0[lane + 32]);
        f4add(a2, p0[lane + 64]); f4add(a3, p0[lane + 96]);
    }

    float ep = 1.0f + eps[0];
    const float4* fn = F + (size_t)node * (D_IN / 4);
    float4 f0 = fn[lane], f1 = fn[lane + 32], f2 = fn[lane + 64], f3 = fn[lane + 96];
    float4 r0 = make_float4(fmaf(ep, f0.x, a0.x), fmaf(ep, f0.y, a0.y), fmaf(ep, f0.z, a0.z), fmaf(ep, f0.w, a0.w));
    float4 r1 = make_float4(fmaf(ep, f1.x, a1.x), fmaf(ep, f1.y, a1.y), fmaf(ep, f1.z, a1.z), fmaf(ep, f1.w, a1.w));
    float4 r2 = make_float4(fmaf(ep, f2.x, a2.x), fmaf(ep, f2.y, a2.y), fmaf(ep, f2.z, a2.z), fmaf(ep, f2.w, a2.w));
    float4 r3 = make_float4(fmaf(ep, f3.x, a3.x), fmaf(ep, f3.y, a3.y), fmaf(ep, f3.z, a3.z), fmaf(ep, f3.w, a3.w));

    size_t base = (size_t)node * D_IN;
    store_split4(g_Ah, g_Al, base + lane * 4,       r0);
    store_split4(g_Ah, g_Al, base + (lane + 32) * 4, r1);
    store_split4(g_Ah, g_Al, base + (lane + 64) * 4, r2);
    store_split4(g_Ah, g_Al, base + (lane + 96) * 4, r3);
}

// ============================================================================
// Weight transpose + split: outh/outl[c][r] = split(in[r][c])
// ============================================================================
__global__ void transpose_split_kernel(const float* __restrict__ in,
                                       __half* __restrict__ outh, __half* __restrict__ outl,
                                       int R, int C) {
    __shared__ float t[32][33];
    int bx = blockIdx.x * 32, by = blockIdx.y * 32;
    int tx = threadIdx.x, ty = threadIdx.y;
    #pragma unroll
    for (int j = 0; j < 32; j += 8)
        t[ty + j][tx] = in[(size_t)(by + ty + j) * C + bx + tx];
    __syncthreads();
    #pragma unroll
    for (int j = 0; j < 32; j += 8) {
        float x = t[tx][ty + j];
        __half h, l; split_h(x, h, l);
        size_t o = (size_t)(bx + ty + j) * R + by + tx;
        outh[o] = h; outl[o] = l;
    }
}

// ============================================================================
// 3xFP16 mma.sync GEMM: out[M,N] = act(A[M,K] @ Bt[N,K]^T + bias) (+residual)
// A/Bt pre-split into hi/lo fp16. acc += Ah*Bh + Ah*Bl + Al*Bh (f32 accum).
// BM=128, BN=128, BK=32, 256 threads (8 warps 2x4, 64x32 warp tiles),
// cp.async double buffer, 80B-padded smem rows (conflict-free frag LDS).
// ============================================================================
#define BM 128
#define BN 128
#define BK 32
#define HROW 40                       // halfs per smem row (32 + 4 pad = 80B)
#define HTILE_H (BM * HROW)           // halfs per tile (5120)
#define HTILE_B (HTILE_H * 2)         // bytes per tile (10240)
#define STAGE_B (4 * HTILE_B)         // Ah,Al,Bh,Bl per stage (40960)
#define GEMM_SMEM (2 * STAGE_B)       // 81920

__device__ __forceinline__ void cp_async16(uint32_t dst, const void* src, int src_sz) {
    asm volatile("cp.async.ca.shared.global [%0], [%1], 16, %2;"
                 :: "r"(dst), "l"(src), "r"(src_sz));
}

__device__ __forceinline__ void load_tile(uint32_t sbase,
                                          const __half* __restrict__ Ah, const __half* __restrict__ Al,
                                          const __half* __restrict__ Bh, const __half* __restrict__ Bl,
                                          int M, int K, int m0, int n0, int k0, int tid) {
    #pragma unroll
    for (int i = 0; i < 2; i++) {
        int idx = tid + i * 256;
        int row = idx >> 2, c8 = idx & 3;
        uint32_t doff = (uint32_t)(row * (HROW * 2) + c8 * 16);
        int gm = m0 + row;
        int ok = gm < M;
        size_t aoff = (size_t)(ok ? gm : 0) * K + k0 + c8 * 8;
        size_t boff = (size_t)(n0 + row) * K + k0 + c8 * 8;
        cp_async16(sbase + doff,                Ah + aoff, ok ? 16 : 0);
        cp_async16(sbase + HTILE_B + doff,      Al + aoff, ok ? 16 : 0);
        cp_async16(sbase + 2 * HTILE_B + doff,  Bh + boff, 16);
        cp_async16(sbase + 3 * HTILE_B + doff,  Bl + boff, 16);
    }
}

__device__ __forceinline__ void mma_f16(float d[4], const uint32_t a[4], const uint32_t b[2]) {
    asm volatile(
        "mma.sync.aligned.m16n8k16.row.col.f32.f16.f16.f32 "
        "{%0,%1,%2,%3}, {%4,%5,%6,%7}, {%8,%9}, {%0,%1,%2,%3};"
        : "+f"(d[0]), "+f"(d[1]), "+f"(d[2]), "+f"(d[3])
        : "r"(a[0]), "r"(a[1]), "r"(a[2]), "r"(a[3]), "r"(b[0]), "r"(b[1]));
}

__global__ __launch_bounds__(256) void gemm_3xh_kernel(
    const __half* __restrict__ Ah, const __half* __restrict__ Al,
    const __half* __restrict__ Bh, const __half* __restrict__ Bl,
    const float* __restrict__ bias, const float* __restrict__ residual,
    float* __restrict__ out, __half* __restrict__ outh, __half* __restrict__ outl,
    int M, int K, int N, int do_relu)
{
    extern __shared__ char smem[];
    uint32_t sb = smem_to_u32(smem);
    const int tid = threadIdx.x, wid = tid >> 5, lane = tid & 31;
    const int m0 = blockIdx.y * BM, n0 = blockIdx.x * BN;
    const int wm = wid & 1, wn = wid >> 1;       // warp tile: 64 (m) x 32 (n)
    const int lg = lane >> 2, lt = lane & 3;

    float acc[4][4][4];
    #pragma unroll
    for (int i = 0; i < 4; i++)
        #pragma unroll
        for (int j = 0; j < 4; j++)
            #pragma unroll
            for (int c = 0; c < 4; c++) acc[i][j][c] = 0.f;

    const int nk = K / BK;
    load_tile(sb, Ah, Al, Bh, Bl, M, K, m0, n0, 0, tid);
    asm volatile("cp.async.commit_group;" ::: "memory");
    if (nk > 1) load_tile(sb + STAGE_B, Ah, Al, Bh, Bl, M, K, m0, n0, BK, tid);
    asm volatile("cp.async.commit_group;" ::: "memory");

    for (int kc = 0; kc < nk; kc++) {
        asm volatile("cp.async.wait_group 1;" ::: "memory");
        __syncthreads();
        const int buf = kc & 1;
        const __half* tAh = (const __half*)(smem + buf * STAGE_B);
        const __half* tAl = tAh + HTILE_H;
        const __half* tBh = tAl + HTILE_H;
        const __half* tBl = tBh + HTILE_H;

        #pragma unroll
        for (int kk = 0; kk < BK; kk += 16) {
            uint32_t bh[4][2], bl[4][2];
            #pragma unroll
            for (int nj = 0; nj < 4; nj++) {
                int n = wn * 32 + nj * 8 + lg;
                int o = n * HROW + kk + 2 * lt;
                bh[nj][0] = *(const uint32_t*)(tBh + o);
                bh[nj][1] = *(const uint32_t*)(tBh + o + 8);
                bl[nj][0] = *(const uint32_t*)(tBl + o);
                bl[nj][1] = *(const uint32_t*)(tBl + o + 8);
            }
            #pragma unroll
            for (int mi = 0; mi < 4; mi++) {
                int r0 = wm * 64 + mi * 16 + lg;
                int o = r0 * HROW + kk + 2 * lt;
                uint32_t ah[4], al[4];
                ah[0] = *(const uint32_t*)(tAh + o);
                ah[1] = *(const uint32_t*)(tAh + o + 8 * HROW);
                ah[2] = *(const uint32_t*)(tAh + o + 8);
                ah[3] = *(const uint32_t*)(tAh + o + 8 * HROW + 8);
                al[0] = *(const uint32_t*)(tAl + o);
                al[1] = *(const uint32_t*)(tAl + o + 8 * HROW);
                al[2] = *(const uint32_t*)(tAl + o + 8);
                al[3] = *(const uint32_t*)(tAl + o + 8 * HROW + 8);
                #pragma unroll
                for (int nj = 0; nj < 4; nj++) {
                    mma_f16(acc[mi][nj], ah, bl[nj]);   // hi*lo
                    mma_f16(acc[mi][nj], al, bh[nj]);   // lo*hi
                    mma_f16(acc[mi][nj], ah, bh[nj]);   // hi*hi
                }
            }
        }
        __syncthreads();
        if (kc + 2 < nk)
            load_tile(sb + (kc & 1) * STAGE_B, Ah, Al, Bh, Bl, M, K, m0, n0, (kc + 2) * BK, tid);
        asm volatile("cp.async.commit_group;" ::: "memory");
    }

    // ---- Epilogue
    #pragma unroll
    for (int mi = 0; mi < 4; mi++) {
        #pragma unroll
        for (int half = 0; half < 2; half++) {
            int gm = m0 + wm * 64 + mi * 16 + lg + half * 8;
            if (gm >= M) continue;
            #pragma unroll
            for (int nj = 0; nj < 4; nj++) {
                int gn = n0 + wn * 32 + nj * 8 + 2 * lt;
                float vx = acc[mi][nj][half * 2 + 0];
                float vy = acc[mi][nj][half * 2 + 1];
                float2 bv = *(const float2*)(bias + gn);
                vx += bv.x; vy += bv.y;
                if (do_relu) { vx = fmaxf(vx, 0.f); vy = fmaxf(vy, 0.f); }
                if (outh) {
                    __half hx, hy, lx, ly;
                    split_h(vx, hx, lx); split_h(vy, hy, ly);
                    *(__half2*)(outh + (size_t)gm * N + gn) = __halves2half2(hx, hy);
                    *(__half2*)(outl + (size_t)gm * N + gn) = __halves2half2(lx, ly);
                } else {
                    if (residual) {
                        float2 rv = *(const float2*)(residual + (size_t)gm * N + gn);
                        vx += rv.x; vy += rv.y;
                    }
                    *(float2*)(out + (size_t)gm * N + gn) = make_float2(vx, vy);
                }
            }
        }
    }
}

// ============================================================================
// kernel_launch
// ============================================================================
extern "C" void kernel_launch(void* const* d_in, const int* in_sizes, int n_in,
                              void* d_out, int out_size) {
    const float* feat = (const float*)d_in[0];
    const float* W1   = (const float*)d_in[1];
    const float* b1   = (const float*)d_in[2];
    const float* W2   = (const float*)d_in[3];
    const float* b2   = (const float*)d_in[4];
    const float* eps  = (const float*)d_in[5];
    const int*   src  = (const int*)d_in[6];
    const int*   dst  = (const int*)d_in[7];
    float* out = (float*)d_out;

    __half *p_Ah, *p_Al, *p_Hh, *p_Hl, *p_W1h, *p_W1l, *p_W2h, *p_W2l;
    cudaGetSymbolAddress((void**)&p_Ah,  g_Ah);
    cudaGetSymbolAddress((void**)&p_Al,  g_Al);
    cudaGetSymbolAddress((void**)&p_Hh,  g_Hh);
    cudaGetSymbolAddress((void**)&p_Hl,  g_Hl);
    cudaGetSymbolAddress((void**)&p_W1h, g_W1h);
    cudaGetSymbolAddress((void**)&p_W1l, g_W1l);
    cudaGetSymbolAddress((void**)&p_W2h, g_W2h);
    cudaGetSymbolAddress((void**)&p_W2l, g_W2l);

    cudaFuncSetAttribute(gemm_3xh_kernel,
                         cudaFuncAttributeMaxDynamicSharedMemorySize, GEMM_SMEM);

    // --- CSR build
    zero_cnt_kernel<<<(N_NODES + 255) / 256, 256>>>();
    hist_kernel<<<N_EDGES / 256, 256>>>(dst);
    scan_kernel<<<1, 1024>>>();
    scatter_kernel<<<N_EDGES / 256, 256>>>(src, dst);

    // --- Weight transpose + split
    transpose_split_kernel<<<dim3(D_HID / 32, D_IN / 32), dim3(32, 8)>>>(W1, p_W1h, p_W1l, D_IN, D_HID);
    transpose_split_kernel<<<dim3(D_IN / 32, D_HID / 32), dim3(32, 8)>>>(W2, p_W2h, p_W2l, D_HID, D_IN);

    // --- Aggregate + GIN combine (writes split rst)
    aggregate_kernel<<<(N_NODES + 7) / 8, 256>>>(feat, eps);

    // --- GEMM1: H = relu(rst @ W1 + b1), written split  [10000,512]@[512,1024]
    gemm_3xh_kernel<<<dim3(D_HID / BN, (N_NODES + BM - 1) / BM), 256, GEMM_SMEM>>>(
        p_Ah, p_Al, p_W1h, p_W1l, b1, nullptr, nullptr, p_Hh, p_Hl,
        N_NODES, D_IN, D_HID, 1);

    // --- GEMM2: out = H @ W2 + b2 + feat  [10000,1024]@[1024,512]
    gemm_3xh_kernel<<<dim3(D_IN / BN, (N_NODES + BM - 1) / BM), 256, GEMM_SMEM>>>(
        p_Hh, p_Hl, p_W2h, p_W2l, b2, feat, out, nullptr, nullptr,
        N_NODES, D_HID, D_IN, 0);
}